// round 17
// baseline (speedup 1.0000x reference)
#include <cuda_runtime.h>
#include <cuda_bf16.h>
#include <stdint.h>
#include <math.h>

#define NIMG   80
#define NQIMG  30
#define S1     84
#define S2     42
#define S3     21
#define DCH    64
#define HW3    (S3*S3)      // 441
#define MDIM   (5*HW3)      // 2205
#define QPAD   512
#define SPAD   2304
#define LRELU_SLOPE 0.2f

typedef unsigned long long ull;
typedef unsigned int u32;

__device__ float g_buf1[(size_t)NIMG*DCH*S1*S1];
__device__ float g_buf2[(size_t)NIMG*DCH*S2*S2];
__device__ float g_buf3[(size_t)NIMG*DCH*S2*S2];
__device__ float g_buf4[(size_t)NIMG*DCH*S3*S3];
__device__ float g_buf5[(size_t)NIMG*DCH*S3*S3];
__device__ float g_buf6[(size_t)NIMG*DCH*S3*S3];
__device__ float g_buf7[(size_t)NIMG*DCH*S3*S3];
__device__ __nv_bfloat16 g_qbf[(size_t)NQIMG*QPAD*DCH];
__device__ __nv_bfloat16 g_sbf[(size_t)10*SPAD*DCH];
__device__ float g_stat[4][2][DCH][2];   // [stage][grp][ch][{sum,sumsq}]

// ---------------- helpers ----------------
__device__ __forceinline__ ull pack2(float lo, float hi) {
    ull r; asm("mov.b64 %0, {%1, %2};" : "=l"(r) : "f"(lo), "f"(hi)); return r;
}
__device__ __forceinline__ ull dup2(float x) {
    ull r; asm("mov.b64 %0, {%1, %2};" : "=l"(r) : "f"(x), "f"(x)); return r;
}
__device__ __forceinline__ ull ffma2(ull a, ull b, ull c) {
    ull d; asm("fma.rn.f32x2 %0, %1, %2, %3;" : "=l"(d) : "l"(a), "l"(b), "l"(c)); return d;
}
__device__ __forceinline__ float2 unpack2(ull v) {
    float2 f; asm("mov.b64 {%0, %1}, %2;" : "=f"(f.x), "=f"(f.y) : "l"(v)); return f;
}
__device__ __forceinline__ u32 bf2pack(float a, float b) {
    __nv_bfloat162 t = __floats2bfloat162_rn(a, b);
    return *(u32*)&t;
}
// stage stats -> (scale, shift) for one (grp, ch)
template <int STAGE>
__device__ __forceinline__ float2 bn_ac(int grp, int ch,
                                        const float* g, const float* b) {
    const int S = (STAGE == 0) ? S1 : (STAGE == 1) ? S2 : S3;
    float cnt = (float)((grp ? (NIMG - NQIMG) : NQIMG) * S * S);
    float m   = g_stat[STAGE][grp][ch][0] / cnt;
    float var = g_stat[STAGE][grp][ch][1] / cnt - m * m;
    float a = g[ch] * rsqrtf(var + 1e-5f);
    return make_float2(a, b[ch] - m * a);
}

#define TOPK3(t0, t1, t2, val)                                   \
    do { float _v = (val);                                       \
        if (_v > (t2)) {                                         \
            if (_v > (t0))      { (t2)=(t1); (t1)=(t0); (t0)=_v; } \
            else if (_v > (t1)) { (t2)=(t1); (t1)=_v; }          \
            else                { (t2)=_v; }                     \
        } } while (0)

// ---------------------------------------------------------------------------
__global__ void zero_misc_kernel(float* out) {
    int tid = threadIdx.x;
    float* st = &g_stat[0][0][0][0];
    if (tid < 1024) st[tid] = 0.f;
    if (tid < 150)  out[tid] = 0.f;
}

// ---------------------------------------------------------------------------
// conv1: 3 -> 64, 84x84 SAME, with FUSED stage-0 BN stats accumulation.
// ---------------------------------------------------------------------------
__global__ __launch_bounds__(256)
void conv1_kernel(const float* __restrict__ q,
                  const float* __restrict__ s,
                  const float* __restrict__ W1) {
    __shared__ float img[3 * 23 * 86];
    __shared__ float wsm[64 * 27];
    __shared__ float stS[64], stQ[64];
    int tid = threadIdx.x, n = blockIdx.y, ty = blockIdx.x;
    int lane = tid & 31;
    const float* src = (n < NQIMG) ? q + (size_t)n * 3 * S1 * S1
                                   : s + (size_t)(n - NQIMG) * 3 * S1 * S1;
    if (tid < 64) { stS[tid] = 0.f; stQ[tid] = 0.f; }
    for (int i = tid; i < 64 * 27; i += 256) wsm[i] = W1[i];
    for (int i = tid; i < 3 * 23 * 86; i += 256) {
        int ci = i / (23 * 86);
        int r  = (i / 86) % 23;
        int c  = i % 86;
        int gy = ty * 21 + r - 1, gx = c - 1;
        img[i] = ((unsigned)gy < S1 && (unsigned)gx < S1)
                     ? src[ci * S1 * S1 + gy * S1 + gx] : 0.f;
    }
    __syncthreads();
    bool act = tid < 252;
    int yl = tid / 12, x0 = (tid % 12) * 7;
    int gy = ty * 21 + yl;

    for (int cb = 0; cb < 8; cb++) {
        float acc[8][7];
#pragma unroll
        for (int c = 0; c < 8; c++)
#pragma unroll
            for (int px = 0; px < 7; px++) acc[c][px] = 0.f;
        if (act) {
#pragma unroll
            for (int ci = 0; ci < 3; ci++) {
                float inr[27];
#pragma unroll
                for (int r = 0; r < 3; r++)
#pragma unroll
                    for (int c = 0; c < 9; c++)
                        inr[r * 9 + c] = img[ci * 23 * 86 + (yl + r) * 86 + x0 + c];
#pragma unroll
                for (int k = 0; k < 9; k++) {
                    int dy = k / 3, dx = k % 3;
                    float wk[8];
#pragma unroll
                    for (int c = 0; c < 8; c++)
                        wk[c] = wsm[(cb * 8 + c) * 27 + ci * 9 + k];
#pragma unroll
                    for (int c = 0; c < 8; c++)
#pragma unroll
                        for (int px = 0; px < 7; px++)
                            acc[c][px] += inr[dy * 9 + px + dx] * wk[c];
                }
            }
        }
#pragma unroll
        for (int c = 0; c < 8; c++) {
            float sv = 0.f, qv = 0.f;
            if (act) {
                int co = cb * 8 + c;
                float* op = g_buf1 + ((size_t)n * DCH + co) * (S1 * S1) + gy * S1 + x0;
#pragma unroll
                for (int px = 0; px < 7; px++) {
                    float v = acc[c][px];
                    op[px] = v;
                    sv += v;
                    qv += v * v;
                }
            }
#pragma unroll
            for (int off = 16; off > 0; off >>= 1) {
                sv += __shfl_down_sync(0xffffffffu, sv, off);
                qv += __shfl_down_sync(0xffffffffu, qv, off);
            }
            if (lane == 0) {
                atomicAdd(&stS[cb * 8 + c], sv);
                atomicAdd(&stQ[cb * 8 + c], qv);
            }
        }
    }
    __syncthreads();
    if (tid < 64) {
        int grp = (n < NQIMG) ? 0 : 1;
        atomicAdd(&g_stat[0][grp][tid][0], stS[tid]);
        atomicAdd(&g_stat[0][grp][tid][1], stQ[tid]);
    }
}

// ---------------------------------------------------------------------------
// conv 64->64 @42, f32x2, FULL ci reduction (no K-split), 2 channels staged
// per sync. grid (16, 80), 256 thr, 4 output channels per block.
// buf2 -> buf3.
// ---------------------------------------------------------------------------
__global__ __launch_bounds__(256)
void conv42_kernel(const float* __restrict__ W) {
    constexpr int S = S2, SP = S + 2, SPSP = SP * SP, SS = S * S;
    constexpr int STRIPS = S / 7, NPOS = STRIPS * S, NT = 256;

    __shared__ float plane[2][2][SPSP];   // [buf][subchannel][...]
    __shared__ ull wsm2[2 * 64 * 9];      // [cp][ci][k]

    int tid = threadIdx.x;
    int n = blockIdx.y;
    int cobase = blockIdx.x * 4;

    for (int i = tid; i < 2 * 64 * 9; i += NT) {
        int cp = i / 576, rem = i % 576;
        int ic = rem / 9, k = rem % 9;
        float w0 = W[(cobase + cp * 2) * 576 + ic * 9 + k];
        float w1 = W[(cobase + cp * 2 + 1) * 576 + ic * 9 + k];
        wsm2[i] = pack2(w0, w1);
    }

    bool active = tid < NPOS;
    int y = tid / STRIPS, x0 = (tid % STRIPS) * 7;

    ull acc[2][7];
#pragma unroll
    for (int cp = 0; cp < 2; cp++)
#pragma unroll
        for (int px = 0; px < 7; px++) acc[cp][px] = 0ull;

    const float* ibase = g_buf2 + (size_t)n * DCH * SS;

    // stage channels {0,1} into buffer 0
    for (int i = tid; i < 2 * SPSP; i += NT) {
        int sub = i / SPSP, j = i - sub * SPSP;
        int yy = j / SP - 1, xx = j % SP - 1;
        plane[0][sub][j] = ((unsigned)yy < S && (unsigned)xx < S)
                               ? ibase[sub * SS + yy * S + xx] : 0.f;
    }

    for (int icp = 0; icp < 32; icp++) {
        __syncthreads();
        if (icp + 1 < 32) {
            const float* src = ibase + (size_t)(2 * icp + 2) * SS;
            int b = (icp + 1) & 1;
            for (int i = tid; i < 2 * SPSP; i += NT) {
                int sub = i / SPSP, j = i - sub * SPSP;
                int yy = j / SP - 1, xx = j % SP - 1;
                plane[b][sub][j] = ((unsigned)yy < S && (unsigned)xx < S)
                                       ? src[sub * SS + yy * S + xx] : 0.f;
            }
        }
        if (active) {
#pragma unroll
            for (int sub = 0; sub < 2; sub++) {
                int ci = 2 * icp + sub;
                const float* pb = plane[icp & 1][sub];
#pragma unroll
                for (int dy = 0; dy < 3; dy++) {
                    ull inr2[9];
#pragma unroll
                    for (int c = 0; c < 9; c++)
                        inr2[c] = dup2(pb[(y + dy) * SP + x0 + c]);
#pragma unroll
                    for (int dx = 0; dx < 3; dx++) {
                        int k = dy * 3 + dx;
#pragma unroll
                        for (int cp = 0; cp < 2; cp++) {
                            ull wk = wsm2[(cp * 64 + ci) * 9 + k];
#pragma unroll
                            for (int px = 0; px < 7; px++)
                                acc[cp][px] = ffma2(inr2[px + dx], wk, acc[cp][px]);
                        }
                    }
                }
            }
        }
    }
    if (active) {
#pragma unroll
        for (int cp = 0; cp < 2; cp++) {
            float* o0 = g_buf3 + ((size_t)n * DCH + cobase + 2 * cp) * SS + y * S + x0;
            float* o1 = o0 + SS;
#pragma unroll
            for (int px = 0; px < 7; px++) {
                float2 f = unpack2(acc[cp][px]);
                o0[px] = f.x;
                o1[px] = f.y;
            }
        }
    }
}

// ---------------------------------------------------------------------------
// conv 64->64 @21, f32x2, FULL ci reduction, TWO images per block (128 thr),
// 2 channels staged per sync, 4 output channels per block. grid (16, 40).
// STAGE: 1 buf4 -> buf5, 2 buf6 -> buf7
// ---------------------------------------------------------------------------
template <int STAGE>
__global__ __launch_bounds__(128)
void conv21_kernel(const float* __restrict__ W) {
    constexpr int S = S3, SP = S + 2, SPSP = SP * SP, SS = S * S;
    constexpr int STRIPS = S / 7, NPOS = STRIPS * S;   // 63
    const float* in = (STAGE == 1) ? g_buf4 : g_buf6;
    float*      out = (STAGE == 1) ? g_buf5 : g_buf7;

    __shared__ float plane[2][2][2][SPSP];   // [img][buf][sub][...]
    __shared__ ull wsm2[2 * 64 * 9];

    int tid = threadIdx.x;
    int img = tid >> 6, ltid = tid & 63;
    int n = blockIdx.y * 2 + img;
    int cobase = blockIdx.x * 4;

    for (int i = tid; i < 2 * 64 * 9; i += 128) {
        int cp = i / 576, rem = i % 576;
        int ic = rem / 9, k = rem % 9;
        float w0 = W[(cobase + cp * 2) * 576 + ic * 9 + k];
        float w1 = W[(cobase + cp * 2 + 1) * 576 + ic * 9 + k];
        wsm2[i] = pack2(w0, w1);
    }

    bool active = ltid < NPOS;
    int y = ltid / STRIPS, x0 = (ltid % STRIPS) * 7;

    ull acc[2][7];
#pragma unroll
    for (int cp = 0; cp < 2; cp++)
#pragma unroll
        for (int px = 0; px < 7; px++) acc[cp][px] = 0ull;

    const float* ibase = in + (size_t)n * DCH * SS;

    for (int i = ltid; i < 2 * SPSP; i += 64) {
        int sub = i / SPSP, j = i - sub * SPSP;
        int yy = j / SP - 1, xx = j % SP - 1;
        plane[img][0][sub][j] = ((unsigned)yy < S && (unsigned)xx < S)
                                    ? ibase[sub * SS + yy * S + xx] : 0.f;
    }

    for (int icp = 0; icp < 32; icp++) {
        __syncthreads();
        if (icp + 1 < 32) {
            const float* src = ibase + (size_t)(2 * icp + 2) * SS;
            int b = (icp + 1) & 1;
            for (int i = ltid; i < 2 * SPSP; i += 64) {
                int sub = i / SPSP, j = i - sub * SPSP;
                int yy = j / SP - 1, xx = j % SP - 1;
                plane[img][b][sub][j] = ((unsigned)yy < S && (unsigned)xx < S)
                                            ? src[sub * SS + yy * S + xx] : 0.f;
            }
        }
        if (active) {
#pragma unroll
            for (int sub = 0; sub < 2; sub++) {
                int ci = 2 * icp + sub;
                const float* pb = plane[img][icp & 1][sub];
#pragma unroll
                for (int dy = 0; dy < 3; dy++) {
                    ull inr2[9];
#pragma unroll
                    for (int c = 0; c < 9; c++)
                        inr2[c] = dup2(pb[(y + dy) * SP + x0 + c]);
#pragma unroll
                    for (int dx = 0; dx < 3; dx++) {
                        int k = dy * 3 + dx;
#pragma unroll
                        for (int cp = 0; cp < 2; cp++) {
                            ull wk = wsm2[(cp * 64 + ci) * 9 + k];
#pragma unroll
                            for (int px = 0; px < 7; px++)
                                acc[cp][px] = ffma2(inr2[px + dx], wk, acc[cp][px]);
                        }
                    }
                }
            }
        }
    }
    if (active) {
#pragma unroll
        for (int cp = 0; cp < 2; cp++) {
            float* o0 = out + ((size_t)n * DCH + cobase + 2 * cp) * SS + y * S + x0;
            float* o1 = o0 + SS;
#pragma unroll
            for (int px = 0; px < 7; px++) {
                float2 f = unpack2(acc[cp][px]);
                o0[px] = f.x;
                o1[px] = f.y;
            }
        }
    }
}

// ---------------------------------------------------------------------------
// BN partial stats (single input) -> g_stat[STAGE] via atomics.
// STAGE 1: buf3(42), 2: buf5(21), 3: buf7(21)
// ---------------------------------------------------------------------------
template <int STAGE>
__global__ void bn_stats_part_kernel() {
    const float* in = (STAGE == 1) ? g_buf3 : (STAGE == 2) ? g_buf5 : g_buf7;
    const int S = (STAGE == 1) ? S2 : S3;
    int ch  = blockIdx.x;
    int grp = blockIdx.y;
    int z   = blockIdx.z;
    int NS  = gridDim.z;
    int n0 = grp ? NQIMG : 0;
    int cnt = grp ? (NIMG - NQIMG) : NQIMG;
    int SS = S * S;
    long total = (long)cnt * SS;
    long len = (total + NS - 1) / NS;
    long i0 = (long)z * len;
    long i1 = min(total, i0 + len);
    float sum = 0.f, sumsq = 0.f;
    for (long i = i0 + threadIdx.x; i < i1; i += blockDim.x) {
        int n = n0 + (int)(i / SS);
        int p = (int)(i % SS);
        float v = in[((size_t)n * DCH + ch) * SS + p];
        sum += v;
        sumsq += v * v;
    }
    __shared__ float s1[256], s2[256];
    int tid = threadIdx.x;
    s1[tid] = sum; s2[tid] = sumsq;
    __syncthreads();
    for (int off = 128; off > 0; off >>= 1) {
        if (tid < off) { s1[tid] += s1[tid + off]; s2[tid] += s2[tid + off]; }
        __syncthreads();
    }
    if (tid == 0) {
        atomicAdd(&g_stat[STAGE][grp][ch][0], s1[0]);
        atomicAdd(&g_stat[STAGE][grp][ch][1], s2[0]);
    }
}

// ---------------------------------------------------------------------------
// BN(inline A/C) + LeakyReLU + 2x2 maxpool.
// STAGE 0: buf1(84)->buf2(42). STAGE 1: buf3(42)->buf4(21).
// ---------------------------------------------------------------------------
template <int STAGE>
__global__ __launch_bounds__(256)
void bn_pool_kernel(const float* __restrict__ g, const float* __restrict__ b) {
    const float* in = (STAGE == 0) ? g_buf1 : g_buf3;
    float*      out = (STAGE == 0) ? g_buf2 : g_buf4;
    const int S  = (STAGE == 0) ? S1 : S2;
    const int So = S / 2;
    __shared__ float sA[128], sC[128];
    if (threadIdx.x < 128) {
        float2 ac = bn_ac<STAGE>(threadIdx.x >> 6, threadIdx.x & 63, g, b);
        sA[threadIdx.x] = ac.x; sC[threadIdx.x] = ac.y;
    }
    __syncthreads();
    long total = (long)NIMG * DCH * So * So;
    long idx = (long)blockIdx.x * blockDim.x + threadIdx.x;
    if (idx >= total) return;
    int SoSo = So * So;
    int p  = (int)(idx % SoSo);
    long t = idx / SoSo;
    int ch = (int)(t % DCH);
    int n  = (int)(t / DCH);
    int gi = ((n < NQIMG) ? 0 : 64) + ch;
    float a = sA[gi], c = sC[gi];
    int yo = p / So, xo = p % So;
    size_t base = ((size_t)n * DCH + ch) * S * S;
    float m = -1e30f;
#pragma unroll
    for (int dy = 0; dy < 2; dy++)
#pragma unroll
        for (int dx = 0; dx < 2; dx++) {
            float v = in[base + (2 * yo + dy) * S + (2 * xo + dx)] * a + c;
            v = (v > 0.f) ? v : LRELU_SLOPE * v;
            m = fmaxf(m, v);
        }
    out[idx] = m;
}

// ---------------------------------------------------------------------------
// BN(stage2) + LeakyReLU: buf5 -> buf6, S=21.
// ---------------------------------------------------------------------------
__global__ __launch_bounds__(256)
void bn_act_kernel(const float* __restrict__ g, const float* __restrict__ b) {
    __shared__ float sA[128], sC[128];
    if (threadIdx.x < 128) {
        float2 ac = bn_ac<2>(threadIdx.x >> 6, threadIdx.x & 63, g, b);
        sA[threadIdx.x] = ac.x; sC[threadIdx.x] = ac.y;
    }
    __syncthreads();
    long total = (long)NIMG * DCH * HW3;
    long idx = (long)blockIdx.x * blockDim.x + threadIdx.x;
    if (idx >= total) return;
    long t = idx / HW3;
    int ch = (int)(t % DCH);
    int n  = (int)(t / DCH);
    int gi = ((n < NQIMG) ? 0 : 64) + ch;
    float v = g_buf5[idx] * sA[gi] + sC[gi];
    g_buf6[idx] = (v > 0.f) ? v : LRELU_SLOPE * v;
}

// ---------------------------------------------------------------------------
// Fused: BN(stage3) + LeakyReLU + L2-normalize + bf16 scatter. (buf7)
// ---------------------------------------------------------------------------
__global__ __launch_bounds__(160)
void bn_norm_kernel(const float* __restrict__ g, const float* __restrict__ b) {
    int n = blockIdx.x;
    int l = blockIdx.y * 147 + threadIdx.x;
    int grp = (n < NQIMG) ? 0 : 1;
    __shared__ float sA[64], sC[64];
    if (threadIdx.x < 64) {
        float2 ac = bn_ac<3>(grp, threadIdx.x, g, b);
        sA[threadIdx.x] = ac.x; sC[threadIdx.x] = ac.y;
    }
    __syncthreads();
    if (threadIdx.x >= 147 || l >= HW3) return;

    const float* pa = g_buf7 + (size_t)n * DCH * HW3 + l;
    float v[64];
    float ss = 0.f;
#pragma unroll
    for (int ch = 0; ch < 64; ch++) {
        float x = pa[ch * HW3] * sA[ch] + sC[ch];
        x = (x > 0.f) ? x : LRELU_SLOPE * x;
        v[ch] = x;
        ss += x * x;
    }
    float inv = 1.f / fmaxf(sqrtf(ss), 1e-12f);

    __nv_bfloat16* dst;
    if (n < NQIMG) {
        dst = g_qbf + ((size_t)n * QPAD + l) * DCH;
    } else {
        int sn = n - NQIMG;
        int bb = sn / 25;
        int w  = (sn % 25) / 5;
        int sh = sn % 5;
        int sw = bb * 5 + w;
        int m  = sh * HW3 + l;
        dst = g_sbf + ((size_t)sw * SPAD + m) * DCH;
    }
#pragma unroll
    for (int c8 = 0; c8 < 64; c8 += 8) {
        uint4 u;
        u.x = bf2pack(v[c8 + 0] * inv, v[c8 + 1] * inv);
        u.y = bf2pack(v[c8 + 2] * inv, v[c8 + 3] * inv);
        u.z = bf2pack(v[c8 + 4] * inv, v[c8 + 5] * inv);
        u.w = bf2pack(v[c8 + 6] * inv, v[c8 + 7] * inv);
        *(uint4*)(dst + c8) = u;
    }
}

// ---------------------------------------------------------------------------
// Tensor-core similarity + fused top-3 + sum. (proven)
// ---------------------------------------------------------------------------
__global__ __launch_bounds__(512)
void sim_mma_kernel(float* __restrict__ out) {
    int mblk = blockIdx.x;
    int w    = blockIdx.y;
    int bq   = blockIdx.z;
    int sw   = (bq / 15) * 5 + w;
    int tid  = threadIdx.x;
    int warp = tid >> 5, lane = tid & 31;
    int g = lane >> 2, tg = lane & 3;

    int m0 = mblk * 256 + warp * 16;
    int r0 = m0 + g, r1 = r0 + 8;

    const __nv_bfloat16* qb = g_qbf + (size_t)bq * QPAD * DCH;
    u32 af[4][4];
#pragma unroll
    for (int kc = 0; kc < 4; kc++) {
        int c0 = kc * 16 + tg * 2;
        af[kc][0] = *(const u32*)(qb + (size_t)r0 * DCH + c0);
        af[kc][1] = *(const u32*)(qb + (size_t)r1 * DCH + c0);
        af[kc][2] = *(const u32*)(qb + (size_t)r0 * DCH + c0 + 8);
        af[kc][3] = *(const u32*)(qb + (size_t)r1 * DCH + c0 + 8);
    }

    float t0a = -1e30f, t1a = -1e30f, t2a = -1e30f;
    float t0b = -1e30f, t1b = -1e30f, t2b = -1e30f;

    __shared__ uint4 ssm[256 * 8];
    const uint4* sp = (const uint4*)(g_sbf + (size_t)sw * SPAD * DCH);

    for (int ch = 0; ch < 9; ch++) {
        __syncthreads();
        for (int i = tid; i < 2048; i += 512) {
            int nn = i >> 3, j = i & 7;
            ssm[(nn << 3) + (j ^ (nn & 7))] = sp[ch * 2048 + i];
        }
        __syncthreads();
        int nbase_ch = ch * 256;
        int tmax = (ch == 8) ? 20 : 32;
        for (int t = 0; t < tmax; t++) {
            int nl = (t << 3) + g;
            const u32* srow = (const u32*)ssm + ((size_t)nl << 5);
            float c0 = 0.f, c1 = 0.f, c2 = 0.f, c3 = 0.f;
#pragma unroll
            for (int kc = 0; kc < 4; kc++) {
                u32 b0 = srow[(((kc * 2)     ^ g) << 2) + tg];
                u32 b1 = srow[(((kc * 2 + 1) ^ g) << 2) + tg];
                asm volatile(
                    "mma.sync.aligned.m16n8k16.row.col.f32.bf16.bf16.f32 "
                    "{%0,%1,%2,%3}, {%4,%5,%6,%7}, {%8,%9}, {%0,%1,%2,%3};"
                    : "+f"(c0), "+f"(c1), "+f"(c2), "+f"(c3)
                    : "r"(af[kc][0]), "r"(af[kc][1]), "r"(af[kc][2]), "r"(af[kc][3]),
                      "r"(b0), "r"(b1));
            }
            int col0 = nbase_ch + (t << 3) + tg * 2;
            if (col0 < MDIM)     { TOPK3(t0a, t1a, t2a, c0); TOPK3(t0b, t1b, t2b, c2); }
            if (col0 + 1 < MDIM) { TOPK3(t0a, t1a, t2a, c1); TOPK3(t0b, t1b, t2b, c3); }
        }
    }

#pragma unroll
    for (int d = 1; d < 4; d <<= 1) {
        float m0a = __shfl_xor_sync(0xffffffffu, t0a, d);
        float m1a = __shfl_xor_sync(0xffffffffu, t1a, d);
        float m2a = __shfl_xor_sync(0xffffffffu, t2a, d);
        TOPK3(t0a, t1a, t2a, m0a); TOPK3(t0a, t1a, t2a, m1a); TOPK3(t0a, t1a, t2a, m2a);
        float m0b = __shfl_xor_sync(0xffffffffu, t0b, d);
        float m1b = __shfl_xor_sync(0xffffffffu, t1b, d);
        float m2b = __shfl_xor_sync(0xffffffffu, t2b, d);
        TOPK3(t0b, t1b, t2b, m0b); TOPK3(t0b, t1b, t2b, m1b); TOPK3(t0b, t1b, t2b, m2b);
    }

    float v = 0.f;
    if (tg == 0) {
        if (r0 < HW3) v += t0a + t1a + t2a;
        if (r1 < HW3) v += t0b + t1b + t2b;
    }
#pragma unroll
    for (int off = 16; off > 0; off >>= 1)
        v += __shfl_down_sync(0xffffffffu, v, off);

    __shared__ float red[16];
    if (lane == 0) red[warp] = v;
    __syncthreads();
    if (warp == 0) {
        float x = (lane < 16) ? red[lane] : 0.f;
#pragma unroll
        for (int off = 8; off > 0; off >>= 1)
            x += __shfl_down_sync(0xffffffffu, x, off);
        if (lane == 0) atomicAdd(&out[bq * 5 + w], x);
    }
}

// ---------------------------------------------------------------------------
// Launcher
// ---------------------------------------------------------------------------
extern "C" void kernel_launch(void* const* d_in, const int* in_sizes, int n_in,
                              void* d_out, int out_size) {
    const float* query   = (const float*)d_in[0];
    const float* support = (const float*)d_in[1];
    const float* W1 = (const float*)d_in[2];
    const float* W2 = (const float*)d_in[3];
    const float* W3 = (const float*)d_in[4];
    const float* W4 = (const float*)d_in[5];
    const float* g1 = (const float*)d_in[6];
    const float* b1 = (const float*)d_in[7];
    const float* g2 = (const float*)d_in[8];
    const float* b2 = (const float*)d_in[9];
    const float* g3 = (const float*)d_in[10];
    const float* b3 = (const float*)d_in[11];
    const float* g4 = (const float*)d_in[12];
    const float* b4 = (const float*)d_in[13];
    float* out = (float*)d_out;

    zero_misc_kernel<<<1, 1024>>>(out);

    // layer 1: conv 3->64 @84 (stats fused), bn+lrelu+pool -> 42
    conv1_kernel<<<dim3(4, 80), 256>>>(query, support, W1);
    {
        long total = (long)NIMG * DCH * S2 * S2;
        bn_pool_kernel<0><<<(int)((total + 255) / 256), 256>>>(g1, b1);
    }
    // layer 2: f32x2 conv @42 (full-K), stats, bn+lrelu+pool -> 21
    conv42_kernel<<<dim3(16, 80), 256>>>(W2);
    bn_stats_part_kernel<1><<<dim3(64, 2, 4), 256>>>();
    {
        long total = (long)NIMG * DCH * S3 * S3;
        bn_pool_kernel<1><<<(int)((total + 255) / 256), 256>>>(g2, b2);
    }
    // layer 3: f32x2 conv @21 (full-K, 2-img), stats, bn+lrelu
    conv21_kernel<1><<<dim3(16, 40), 128>>>(W3);
    bn_stats_part_kernel<2><<<dim3(64, 2, 2), 256>>>();
    {
        long total = (long)NIMG * DCH * HW3;
        bn_act_kernel<<<(int)((total + 255) / 256), 256>>>(g3, b3);
    }
    // layer 4: f32x2 conv @21, stats, fused bn+norm+scatter
    conv21_kernel<2><<<dim3(16, 40), 128>>>(W4);
    bn_stats_part_kernel<3><<<dim3(64, 2, 2), 256>>>();
    bn_norm_kernel<<<dim3(80, 3), 160>>>(g4, b4);
    // tensor-core similarity
    sim_mma_kernel<<<dim3(2, 5, 30), 512>>>(out);
}